// round 16
// baseline (speedup 1.0000x reference)
#include <cuda_runtime.h>
#include <cuda_fp16.h>
#include <math.h>
#include <stdint.h>

// ---------------------------------------------------------------------------
// Problem dims (fixed): B=8, S=1024, D=768, H=12, hd=64
// ---------------------------------------------------------------------------
#define BS   8192
#define DIM  768
#define D4   3072
#define QKVN 2304
#define NH   12
#define HD   64
#define SEQ  1024
#define LN_EPS 1e-5f

// ---------------------------------------------------------------------------
// Static device scratch (fp16 activations / weights; fp32 where precision-critical)
// ---------------------------------------------------------------------------
__device__ __half g_xn  [BS * DIM];
__device__ __half g_qkv [BS * QKVN];
__device__ __half g_att [BS * DIM];
__device__ float  g_y1  [BS * DIM];
__device__ __half g_y2  [BS * DIM];
__device__ __half g_h   [BS * D4];
__device__ __half g_wqkv_t[QKVN * DIM];
__device__ float  g_bqkv[QKVN];
__device__ __half g_wo_t[DIM * DIM];
__device__ __half g_w1_t[D4 * DIM];
__device__ __half g_w2_t[DIM * D4];

__device__ __forceinline__ uint32_t smem_u32(const void* p) {
    uint32_t a;
    asm("{ .reg .u64 t; cvta.to.shared.u64 t, %1; cvt.u32.u64 %0, t; }"
        : "=r"(a) : "l"(p));
    return a;
}

#define MMA_F16(acc, a, b0, b1)                                                \
    asm volatile(                                                              \
        "mma.sync.aligned.m16n8k16.row.col.f32.f16.f16.f32 "                   \
        "{%0,%1,%2,%3}, {%4,%5,%6,%7}, {%8,%9}, {%0,%1,%2,%3};"                \
        : "+f"((acc)[0]), "+f"((acc)[1]), "+f"((acc)[2]), "+f"((acc)[3])       \
        : "r"((a)[0]), "r"((a)[1]), "r"((a)[2]), "r"((a)[3]),                  \
          "r"(b0), "r"(b1))

#define SMW 36
#define TILE_W (128 * SMW)
#define GEMM_SMEM_BYTES (4 * TILE_W * 4)   // 73728 B

// ---------------------------------------------------------------------------
// fp16 GEMM (frozen: 655.5us build): 128x128 tile, BK=64, 8 warps, m16n8k16.
// ---------------------------------------------------------------------------
template <bool GELU, bool RES, bool HOUT>
__global__ __launch_bounds__(256) void h_gemm_kernel(
    const __half* __restrict__ A, const __half* __restrict__ Bt,
    const float* __restrict__ bias, const __half* __restrict__ res,
    void* __restrict__ Cv, int M, int N, int K) {
    extern __shared__ __align__(16) uint32_t smw[];
    uint32_t* Asw = smw;
    uint32_t* Bsw = smw + 2 * TILE_W;

    const int tid  = threadIdx.x;
    const int wid  = tid >> 5;
    const int lane = tid & 31;
    const int g    = lane >> 2;
    const int t4   = lane & 3;
    const int wm   = (wid >> 2) * 64;
    const int wn   = (wid & 3) * 32;

    const int brow = blockIdx.y * 128;
    const int bcol = blockIdx.x * 128;
    const int NCH  = K >> 6;

    float acc[4][4][4];
#pragma unroll
    for (int mt = 0; mt < 4; mt++)
#pragma unroll
        for (int nt = 0; nt < 4; nt++)
#pragma unroll
            for (int r = 0; r < 4; r++) acc[mt][nt][r] = 0.f;

    const uint32_t sA = smem_u32(Asw);
    const uint32_t sB = smem_u32(Bsw);

    auto load_tile = [&](int chunk, int s) {
        const int k0 = chunk * 64;
#pragma unroll
        for (int it = 0; it < 4; it++) {
            int id  = it * 256 + tid;
            int row = id >> 3;
            int cc  = id & 7;
            uint32_t off = (uint32_t)((s * TILE_W + row * SMW + cc * 4) * 4);
            const __half* ga = A + (size_t)(brow + row) * K + k0 + cc * 8;
            asm volatile("cp.async.cg.shared.global [%0], [%1], 16;"
                         :: "r"(sA + off), "l"(ga));
            const __half* gb = Bt + (size_t)(bcol + row) * K + k0 + cc * 8;
            asm volatile("cp.async.cg.shared.global [%0], [%1], 16;"
                         :: "r"(sB + off), "l"(gb));
        }
        asm volatile("cp.async.commit_group;" ::: "memory");
    };

    load_tile(0, 0);
    load_tile(1, 1);

    for (int i = 0; i < NCH; i++) {
        const int s = i & 1;
        if (i < NCH - 1) asm volatile("cp.async.wait_group 1;" ::: "memory");
        else             asm volatile("cp.async.wait_group 0;" ::: "memory");
        __syncthreads();

        const uint32_t* as = Asw + s * TILE_W;
        const uint32_t* bs = Bsw + s * TILE_W;

#pragma unroll
        for (int kk = 0; kk < 4; kk++) {
            uint32_t af[4][4];
#pragma unroll
            for (int mt = 0; mt < 4; mt++) {
                const uint32_t* p = as + (wm + mt * 16 + g) * SMW + kk * 8 + t4;
                af[mt][0] = p[0];
                af[mt][1] = p[8 * SMW];
                af[mt][2] = p[4];
                af[mt][3] = p[8 * SMW + 4];
            }
            uint32_t bf[4][2];
#pragma unroll
            for (int nt = 0; nt < 4; nt++) {
                const uint32_t* p = bs + (wn + nt * 8 + g) * SMW + kk * 8 + t4;
                bf[nt][0] = p[0];
                bf[nt][1] = p[4];
            }
#pragma unroll
            for (int mt = 0; mt < 4; mt++)
#pragma unroll
                for (int nt = 0; nt < 4; nt++)
                    MMA_F16(acc[mt][nt], af[mt], bf[nt][0], bf[nt][1]);
        }
        __syncthreads();
        if (i + 2 < NCH) load_tile(i + 2, s);
    }

#pragma unroll
    for (int mt = 0; mt < 4; mt++) {
        const int row0 = brow + wm + mt * 16 + g;
#pragma unroll
        for (int nt = 0; nt < 4; nt++) {
            const int col = bcol + wn + nt * 8 + t4 * 2;
            const float bx = bias[col], by = bias[col + 1];
#pragma unroll
            for (int hh = 0; hh < 2; hh++) {
                const int row = row0 + hh * 8;
                float vx = acc[mt][nt][2 * hh]     + bx;
                float vy = acc[mt][nt][2 * hh + 1] + by;
                if (GELU) {
                    vx = 0.5f * vx * (1.0f + erff(vx * 0.70710678118654752f));
                    vy = 0.5f * vy * (1.0f + erff(vy * 0.70710678118654752f));
                }
                size_t go = (size_t)row * N + col;
                if (RES) {
                    __half2 rv = *(const __half2*)&res[go];
                    vx += __half2float(rv.x); vy += __half2float(rv.y);
                }
                if (HOUT) {
                    *(__half2*)&((__half*)Cv)[go] = __floats2half2_rn(vx, vy);
                } else {
                    float2 o; o.x = vx; o.y = vy;
                    *(float2*)&((float*)Cv)[go] = o;
                }
            }
        }
    }
}

// ---------------------------------------------------------------------------
// fp16 flash attention, software-pipelined:
// S(i+1) MMAs issued BEFORE softmax(i) so the softmax ALU/MUFU chain overlaps
// tensor-pipe work instead of idling it. 3-stage KV smem ring.
// smem: Q + P + 3*K + 3*V = 8 * 64 * 36 words = 73728 B -> 2 CTAs/SM.
// ---------------------------------------------------------------------------
#define ATT_SMEM_BYTES (8 * 64 * SMW * 4)

__global__ __launch_bounds__(128) void attention_mma_kernel(
    const __half* __restrict__ qkv, __half* __restrict__ out) {
    extern __shared__ __align__(16) uint32_t smw[];
    uint32_t* Qw = smw;                    // 64*36
    uint32_t* Pw = smw + 64 * SMW;         // 64*36
    uint32_t* Kw = smw + 2 * 64 * SMW;     // 3 stages
    uint32_t* Vw = smw + 5 * 64 * SMW;     // 3 stages

    const int b = blockIdx.z, h = blockIdx.y, qt = blockIdx.x;
    const int tid = threadIdx.x, wid = tid >> 5, lane = tid & 31;
    const int g = lane >> 2, t4 = lane & 3;

    const uint32_t sK = smem_u32(Kw), sV = smem_u32(Vw);

    const __half* Qg = qkv + (size_t)(b * SEQ + qt * 64) * QKVN + h * HD;
    const __half* Kg = qkv + (size_t)b * SEQ * QKVN + DIM     + h * HD;
    const __half* Vg = qkv + (size_t)b * SEQ * QKVN + 2 * DIM + h * HD;

    // Q tile: scale by 1/8 (exact in fp16)
    {
        const __half2 sc = __float2half2_rn(0.125f);
#pragma unroll
        for (int it = 0; it < 4; it++) {
            int id = it * 128 + tid;
            int r = id >> 3, cc = id & 7;
            uint4 v = *(const uint4*)(Qg + (size_t)r * QKVN + cc * 8);
            __half2* hv = (__half2*)&v;
            hv[0] = __hmul2(hv[0], sc); hv[1] = __hmul2(hv[1], sc);
            hv[2] = __hmul2(hv[2], sc); hv[3] = __hmul2(hv[3], sc);
            *(uint4*)&Qw[r * SMW + cc * 4] = v;
        }
    }

    auto loadKV = [&](int kb, int s) {
#pragma unroll
        for (int it = 0; it < 4; it++) {
            int id = it * 128 + tid;
            int r = id >> 3, cc = id & 7;
            uint32_t off = (uint32_t)(((s * 64 + r) * SMW + cc * 4) * 4);
            const __half* gk = Kg + (size_t)(kb * 64 + r) * QKVN + cc * 8;
            asm volatile("cp.async.cg.shared.global [%0], [%1], 16;"
                         :: "r"(sK + off), "l"(gk));
            const __half* gv = Vg + (size_t)(kb * 64 + r) * QKVN + cc * 8;
            asm volatile("cp.async.cg.shared.global [%0], [%1], 16;"
                         :: "r"(sV + off), "l"(gv));
        }
        asm volatile("cp.async.commit_group;" ::: "memory");
    };

    loadKV(0, 0);
    loadKV(1, 1);
    loadKV(2, 2);
    asm volatile("cp.async.wait_group 2;" ::: "memory");   // stage 0 ready
    __syncthreads();                                       // Q + stage 0 visible

    const int m0row = wid * 16 + g;
    uint32_t af[4][4];
#pragma unroll
    for (int kt = 0; kt < 4; kt++) {
        const uint32_t* p = Qw + m0row * SMW + kt * 8 + t4;
        af[kt][0] = p[0];
        af[kt][1] = p[8 * SMW];
        af[kt][2] = p[4];
        af[kt][3] = p[8 * SMW + 4];
    }

    const int vrow16 = lane & 15;
    const int vcolw  = (lane >> 4) * 4;

    // S = Q K^T for one stage
    auto computeS = [&](int st, float (*sf)[4]) {
        const uint32_t* ks = Kw + st * 64 * SMW;
#pragma unroll
        for (int nt = 0; nt < 8; nt++)
#pragma unroll
            for (int r = 0; r < 4; r++) sf[nt][r] = 0.f;
#pragma unroll
        for (int kt = 0; kt < 4; kt++) {
#pragma unroll
            for (int nt = 0; nt < 8; nt++) {
                const uint32_t* p = ks + (nt * 8 + g) * SMW + kt * 8 + t4;
                MMA_F16(sf[nt], af[kt], p[0], p[4]);
            }
        }
    };

    float of[8][4];
#pragma unroll
    for (int nt = 0; nt < 8; nt++)
#pragma unroll
        for (int r = 0; r < 4; r++) of[nt][r] = 0.f;
    float m0 = -INFINITY, m1 = -INFINITY, l0 = 0.f, l1 = 0.f;

    float sfa[8][4];
    computeS(0, sfa);                      // S(0)

    for (int i = 0; i < 16; i++) {
        const int s  = i % 3;

        // make next stage visible, then issue S(i+1) MMAs FIRST so the
        // softmax(i) ALU/MUFU chain below overlaps tensor-pipe work.
        if (i < 15) {
            if (i < 14) asm volatile("cp.async.wait_group 1;" ::: "memory");
            else        asm volatile("cp.async.wait_group 0;" ::: "memory");
            __syncthreads();
        }
        float sfn[8][4];
        if (i < 15) computeS((i + 1) % 3, sfn);

        // online softmax on sfa (tile i)
        float tm0 = -INFINITY, tm1 = -INFINITY;
#pragma unroll
        for (int nt = 0; nt < 8; nt++) {
            tm0 = fmaxf(tm0, fmaxf(sfa[nt][0], sfa[nt][1]));
            tm1 = fmaxf(tm1, fmaxf(sfa[nt][2], sfa[nt][3]));
        }
        tm0 = fmaxf(tm0, __shfl_xor_sync(0xffffffffu, tm0, 1));
        tm0 = fmaxf(tm0, __shfl_xor_sync(0xffffffffu, tm0, 2));
        tm1 = fmaxf(tm1, __shfl_xor_sync(0xffffffffu, tm1, 1));
        tm1 = fmaxf(tm1, __shfl_xor_sync(0xffffffffu, tm1, 2));
        const float nm0 = fmaxf(m0, tm0), nm1 = fmaxf(m1, tm1);
        const float a0 = __expf(m0 - nm0), a1 = __expf(m1 - nm1);

        float rs0 = 0.f, rs1 = 0.f;
        uint32_t* pp0 = Pw + m0row * SMW + t4;
        uint32_t* pp1 = Pw + (m0row + 8) * SMW + t4;
#pragma unroll
        for (int nt = 0; nt < 8; nt++) {
            float p0 = __expf(sfa[nt][0] - nm0);
            float p1 = __expf(sfa[nt][1] - nm0);
            float p2 = __expf(sfa[nt][2] - nm1);
            float p3 = __expf(sfa[nt][3] - nm1);
            rs0 += p0 + p1; rs1 += p2 + p3;
            ((__half2*)pp0)[0] = __floats2half2_rn(p0, p1);
            ((__half2*)pp1)[0] = __floats2half2_rn(p2, p3);
            pp0 += 4; pp1 += 4;
        }
        rs0 += __shfl_xor_sync(0xffffffffu, rs0, 1);
        rs0 += __shfl_xor_sync(0xffffffffu, rs0, 2);
        rs1 += __shfl_xor_sync(0xffffffffu, rs1, 1);
        rs1 += __shfl_xor_sync(0xffffffffu, rs1, 2);
        l0 = l0 * a0 + rs0;
        l1 = l1 * a1 + rs1;
#pragma unroll
        for (int nt = 0; nt < 8; nt++) {
            of[nt][0] *= a0; of[nt][1] *= a0;
            of[nt][2] *= a1; of[nt][3] *= a1;
        }
        m0 = nm0; m1 = nm1;

        // O += P V (P rows are warp-local: no sync needed between write/read)
#pragma unroll
        for (int kk = 0; kk < 4; kk++) {
            const uint32_t* pw = Pw + m0row * SMW + kk * 8 + t4;
            uint32_t pf[4];
            pf[0] = pw[0];
            pf[1] = pw[8 * SMW];
            pf[2] = pw[4];
            pf[3] = pw[8 * SMW + 4];
            const uint32_t vrowbase = (uint32_t)(((s * 64 + kk * 16 + vrow16) * SMW + vcolw) * 4);
#pragma unroll
            for (int ntp = 0; ntp < 4; ntp++) {
                uint32_t b00, b01, b10, b11;
                uint32_t addr = sV + vrowbase + (uint32_t)(ntp * 8 * 4);
                asm volatile(
                    "ldmatrix.sync.aligned.m8n8.x4.trans.shared.b16 "
                    "{%0,%1,%2,%3}, [%4];"
                    : "=r"(b00), "=r"(b01), "=r"(b10), "=r"(b11)
                    : "r"(addr));
                MMA_F16(of[2 * ntp],     pf, b00, b01);
                MMA_F16(of[2 * ntp + 1], pf, b10, b11);
            }
        }
        __syncthreads();                  // stage s fully consumed by all warps
        if (i + 3 <= 15) loadKV(i + 3, (i + 3) % 3);

        if (i < 15) {
#pragma unroll
            for (int nt = 0; nt < 8; nt++)
#pragma unroll
                for (int r = 0; r < 4; r++) sfa[nt][r] = sfn[nt][r];
        }
    }

    // epilogue -> half att
    const float i0 = 1.f / l0, i1 = 1.f / l1;
    const int row = b * SEQ + qt * 64 + m0row;
#pragma unroll
    for (int nt = 0; nt < 8; nt++) {
        const int col = h * HD + nt * 8 + 2 * t4;
        *(__half2*)&out[(size_t)row * DIM + col] =
            __floats2half2_rn(of[nt][0] * i0, of[nt][1] * i0);
        *(__half2*)&out[(size_t)(row + 8) * DIM + col] =
            __floats2half2_rn(of[nt][2] * i1, of[nt][3] * i1);
    }
}

// ---------------------------------------------------------------------------
// Repack / transpose / layernorm (frozen)
// ---------------------------------------------------------------------------
__global__ void repack_qkv_t_kernel(const float* __restrict__ Wq, const float* __restrict__ bq,
                                    const float* __restrict__ Wk, const float* __restrict__ bk,
                                    const float* __restrict__ Wv, const float* __restrict__ bv) {
    int idx = blockIdx.x * blockDim.x + threadIdx.x;
    const int total = QKVN * DIM;
    if (idx < total) {
        int n = idx / DIM;
        int d = idx % DIM;
        int t  = n / DIM;
        int h  = (n % DIM) / HD;
        int kk = n % HD;
        const float* W = (t == 0) ? Wq : (t == 1) ? Wk : Wv;
        g_wqkv_t[idx] = __float2half_rn(W[(h * DIM + d) * HD + kk]);
    }
    if (idx < QKVN) {
        int t  = idx / DIM;
        int h  = (idx % DIM) / HD;
        int kk = idx % HD;
        const float* bb = (t == 0) ? bq : (t == 1) ? bk : bv;
        g_bqkv[idx] = bb[h * HD + kk];
    }
}

__global__ void transpose_kernel(const float* __restrict__ in, __half* __restrict__ out,
                                 int R, int C) {
    __shared__ float t[32][33];
    int c0 = blockIdx.x * 32, r0 = blockIdx.y * 32;
    int x = c0 + threadIdx.x;
    for (int dy = threadIdx.y; dy < 32; dy += 8) {
        int r = r0 + dy;
        if (r < R && x < C) t[dy][threadIdx.x] = in[(size_t)r * C + x];
    }
    __syncthreads();
    int y = r0 + threadIdx.x;
    for (int dx = threadIdx.y; dx < 32; dx += 8) {
        int c = c0 + dx;
        if (c < C && y < R) out[(size_t)c * R + y] = __float2half_rn(t[threadIdx.x][dx]);
    }
}

__global__ __launch_bounds__(256) void layernorm_kernel(
    const float* __restrict__ X, const float* __restrict__ gamma,
    const float* __restrict__ beta, __half* __restrict__ Y) {
    const int row = blockIdx.x;
    const float* x = X + (size_t)row * DIM;
    __half*      y = Y + (size_t)row * DIM;
    const int tid = threadIdx.x, wid = tid >> 5, lane = tid & 31;
    __shared__ float red[8];

    float v0 = x[tid], v1 = x[tid + 256], v2 = x[tid + 512];
    float s = v0 + v1 + v2;
#pragma unroll
    for (int o = 16; o > 0; o >>= 1) s += __shfl_xor_sync(0xffffffffu, s, o);
    if (lane == 0) red[wid] = s;
    __syncthreads();
    if (tid < 32) {
        float t = (tid < 8) ? red[tid] : 0.f;
#pragma unroll
        for (int o = 4; o > 0; o >>= 1) t += __shfl_xor_sync(0xffffffffu, t, o);
        if (tid == 0) red[0] = t;
    }
    __syncthreads();
    const float mean = red[0] / (float)DIM;

    float d0 = v0 - mean, d1 = v1 - mean, d2 = v2 - mean;
    float vv = d0 * d0 + d1 * d1 + d2 * d2;
#pragma unroll
    for (int o = 16; o > 0; o >>= 1) vv += __shfl_xor_sync(0xffffffffu, vv, o);
    if (lane == 0) red[wid] = vv;
    __syncthreads();
    if (tid < 32) {
        float t = (tid < 8) ? red[tid] : 0.f;
#pragma unroll
        for (int o = 4; o > 0; o >>= 1) t += __shfl_xor_sync(0xffffffffu, t, o);
        if (tid == 0) red[0] = t;
    }
    __syncthreads();
    const float inv = rsqrtf(red[0] / (float)(DIM - 1) + LN_EPS);

    y[tid]       = __float2half_rn(gamma[tid]       * d0 * inv + beta[tid]);
    y[tid + 256] = __float2half_rn(gamma[tid + 256] * d1 * inv + beta[tid + 256]);
    y[tid + 512] = __float2half_rn(gamma[tid + 512] * d2 * inv + beta[tid + 512]);
}

// ---------------------------------------------------------------------------
// Host launch
// ---------------------------------------------------------------------------
extern "C" void kernel_launch(void* const* d_in, const int* in_sizes, int n_in,
                              void* d_out, int out_size) {
    const float* x   = (const float*)d_in[0];
    const float* Wq  = (const float*)d_in[1];
    const float* bq  = (const float*)d_in[2];
    const float* Wk  = (const float*)d_in[3];
    const float* bk  = (const float*)d_in[4];
    const float* Wv  = (const float*)d_in[5];
    const float* bv  = (const float*)d_in[6];
    const float* Wo  = (const float*)d_in[7];
    const float* bo  = (const float*)d_in[8];
    const float* W1  = (const float*)d_in[9];
    const float* b1  = (const float*)d_in[10];
    const float* W2  = (const float*)d_in[11];
    const float* b2  = (const float*)d_in[12];
    const float* g1  = (const float*)d_in[13];
    const float* be1 = (const float*)d_in[14];
    const float* g2  = (const float*)d_in[15];
    const float* be2 = (const float*)d_in[16];
    float* out = (float*)d_out;

    __half *xn, *qkv, *att, *y2, *hbuf, *wqkv_t, *wo_t, *w1_t, *w2_t;
    float  *y1, *bqkv;
    cudaGetSymbolAddress((void**)&xn,     g_xn);
    cudaGetSymbolAddress((void**)&qkv,    g_qkv);
    cudaGetSymbolAddress((void**)&att,    g_att);
    cudaGetSymbolAddress((void**)&y1,     g_y1);
    cudaGetSymbolAddress((void**)&y2,     g_y2);
    cudaGetSymbolAddress((void**)&hbuf,   g_h);
    cudaGetSymbolAddress((void**)&wqkv_t, g_wqkv_t);
    cudaGetSymbolAddress((void**)&bqkv,   g_bqkv);
    cudaGetSymbolAddress((void**)&wo_t,   g_wo_t);
    cudaGetSymbolAddress((void**)&w1_t,   g_w1_t);
    cudaGetSymbolAddress((void**)&w2_t,   g_w2_t);

    cudaFuncSetAttribute(h_gemm_kernel<false, false, true>,
                         cudaFuncAttributeMaxDynamicSharedMemorySize, GEMM_SMEM_BYTES);
    cudaFuncSetAttribute(h_gemm_kernel<true, false, true>,
                         cudaFuncAttributeMaxDynamicSharedMemorySize, GEMM_SMEM_BYTES);
    cudaFuncSetAttribute(h_gemm_kernel<false, true, false>,
                         cudaFuncAttributeMaxDynamicSharedMemorySize, GEMM_SMEM_BYTES);
    cudaFuncSetAttribute(attention_mma_kernel,
                         cudaFuncAttributeMaxDynamicSharedMemorySize, ATT_SMEM_BYTES);

    {
        int total = QKVN * DIM;
        repack_qkv_t_kernel<<<(total + 255) / 256, 256>>>(Wq, bq, Wk, bk, Wv, bv);
    }
    {
        dim3 blk(32, 8);
        transpose_kernel<<<dim3(DIM / 32, DIM / 32), blk>>>(Wo, wo_t, DIM, DIM);
        transpose_kernel<<<dim3(D4 / 32, DIM / 32), blk>>>(W1, w1_t, DIM, D4);
        transpose_kernel<<<dim3(DIM / 32, D4 / 32), blk>>>(W2, w2_t, D4, DIM);
    }

    // 1. ln1 -> half xn
    layernorm_kernel<<<BS, 256>>>(x, g1, be1, xn);
    // 2. fused QKV gemm -> half qkv
    h_gemm_kernel<false, false, true><<<dim3(QKVN / 128, BS / 128), 256, GEMM_SMEM_BYTES>>>(
        xn, wqkv_t, bqkv, nullptr, qkv, BS, QKVN, DIM);
    // 3. attention (software-pipelined) -> half att
    attention_mma_kernel<<<dim3(SEQ / 64, NH, 8), 128, ATT_SMEM_BYTES>>>(qkv, att);
    // 4. o-proj + residual(xn) -> float y1
    h_gemm_kernel<false, true, false><<<dim3(DIM / 128, BS / 128), 256, GEMM_SMEM_BYTES>>>(
        att, wo_t, bo, xn, y1, BS, DIM, DIM);
    // 5. ln2 -> half y2
    layernorm_kernel<<<BS, 256>>>(y1, g2, be2, y2);
    // 6. ffn up + gelu -> half h
    h_gemm_kernel<true, false, true><<<dim3(D4 / 128, BS / 128), 256, GEMM_SMEM_BYTES>>>(
        y2, w1_t, b1, nullptr, hbuf, BS, D4, DIM);
    // 7. ffn down + residual(y2) -> float out
    h_gemm_kernel<false, true, false><<<dim3(DIM / 128, BS / 128), 256, GEMM_SMEM_BYTES>>>(
        hbuf, w2_t, b2, y2, out, BS, DIM, D4);
}

// round 17
// speedup vs baseline: 1.0394x; 1.0394x over previous
#include <cuda_runtime.h>
#include <cuda_fp16.h>
#include <math.h>
#include <stdint.h>

// ---------------------------------------------------------------------------
// Problem dims (fixed): B=8, S=1024, D=768, H=12, hd=64
// ---------------------------------------------------------------------------
#define BS   8192
#define DIM  768
#define D4   3072
#define QKVN 2304
#define NH   12
#define HD   64
#define SEQ  1024
#define LN_EPS 1e-5f

// ---------------------------------------------------------------------------
// Static device scratch
// ---------------------------------------------------------------------------
__device__ __half g_xn  [BS * DIM];
__device__ __half g_qkv [BS * QKVN];
__device__ __half g_att [BS * DIM];
__device__ float  g_y1  [BS * DIM];
__device__ __half g_y2  [BS * DIM];
__device__ __half g_h   [BS * D4];
__device__ __half g_wqkv_t[QKVN * DIM];
__device__ float  g_bqkv[QKVN];
__device__ __half g_wo_t[DIM * DIM];
__device__ __half g_w1_t[D4 * DIM];
__device__ __half g_w2_t[DIM * D4];

__device__ __forceinline__ uint32_t smem_u32(const void* p) {
    uint32_t a;
    asm("{ .reg .u64 t; cvta.to.shared.u64 t, %1; cvt.u32.u64 %0, t; }"
        : "=r"(a) : "l"(p));
    return a;
}
__device__ __forceinline__ uint32_t h2u(__half2 h) { return *(uint32_t*)&h; }

#define MMA_F16(acc, a, b0, b1)                                                \
    asm volatile(                                                              \
        "mma.sync.aligned.m16n8k16.row.col.f32.f16.f16.f32 "                   \
        "{%0,%1,%2,%3}, {%4,%5,%6,%7}, {%8,%9}, {%0,%1,%2,%3};"                \
        : "+f"((acc)[0]), "+f"((acc)[1]), "+f"((acc)[2]), "+f"((acc)[3])       \
        : "r"((a)[0]), "r"((a)[1]), "r"((a)[2]), "r"((a)[3]),                  \
          "r"(b0), "r"(b1))

#define SMW 36
#define TILE_W (128 * SMW)
#define GEMM_SMEM_BYTES (4 * TILE_W * 4)   // 73728 B

// ---------------------------------------------------------------------------
// fp16 GEMM (frozen: 655.5us build)
// ---------------------------------------------------------------------------
template <bool GELU, bool RES, bool HOUT>
__global__ __launch_bounds__(256) void h_gemm_kernel(
    const __half* __restrict__ A, const __half* __restrict__ Bt,
    const float* __restrict__ bias, const __half* __restrict__ res,
    void* __restrict__ Cv, int M, int N, int K) {
    extern __shared__ __align__(16) uint32_t smw[];
    uint32_t* Asw = smw;
    uint32_t* Bsw = smw + 2 * TILE_W;

    const int tid  = threadIdx.x;
    const int wid  = tid >> 5;
    const int lane = tid & 31;
    const int g    = lane >> 2;
    const int t4   = lane & 3;
    const int wm   = (wid >> 2) * 64;
    const int wn   = (wid & 3) * 32;

    const int brow = blockIdx.y * 128;
    const int bcol = blockIdx.x * 128;
    const int NCH  = K >> 6;

    float acc[4][4][4];
#pragma unroll
    for (int mt = 0; mt < 4; mt++)
#pragma unroll
        for (int nt = 0; nt < 4; nt++)
#pragma unroll
            for (int r = 0; r < 4; r++) acc[mt][nt][r] = 0.f;

    const uint32_t sA = smem_u32(Asw);
    const uint32_t sB = smem_u32(Bsw);

    auto load_tile = [&](int chunk, int s) {
        const int k0 = chunk * 64;
#pragma unroll
        for (int it = 0; it < 4; it++) {
            int id  = it * 256 + tid;
            int row = id >> 3;
            int cc  = id & 7;
            uint32_t off = (uint32_t)((s * TILE_W + row * SMW + cc * 4) * 4);
            const __half* ga = A + (size_t)(brow + row) * K + k0 + cc * 8;
            asm volatile("cp.async.cg.shared.global [%0], [%1], 16;"
                         :: "r"(sA + off), "l"(ga));
            const __half* gb = Bt + (size_t)(bcol + row) * K + k0 + cc * 8;
            asm volatile("cp.async.cg.shared.global [%0], [%1], 16;"
                         :: "r"(sB + off), "l"(gb));
        }
        asm volatile("cp.async.commit_group;" ::: "memory");
    };

    load_tile(0, 0);
    load_tile(1, 1);

    for (int i = 0; i < NCH; i++) {
        const int s = i & 1;
        if (i < NCH - 1) asm volatile("cp.async.wait_group 1;" ::: "memory");
        else             asm volatile("cp.async.wait_group 0;" ::: "memory");
        __syncthreads();

        const uint32_t* as = Asw + s * TILE_W;
        const uint32_t* bs = Bsw + s * TILE_W;

#pragma unroll
        for (int kk = 0; kk < 4; kk++) {
            uint32_t af[4][4];
#pragma unroll
            for (int mt = 0; mt < 4; mt++) {
                const uint32_t* p = as + (wm + mt * 16 + g) * SMW + kk * 8 + t4;
                af[mt][0] = p[0];
                af[mt][1] = p[8 * SMW];
                af[mt][2] = p[4];
                af[mt][3] = p[8 * SMW + 4];
            }
            uint32_t bf[4][2];
#pragma unroll
            for (int nt = 0; nt < 4; nt++) {
                const uint32_t* p = bs + (wn + nt * 8 + g) * SMW + kk * 8 + t4;
                bf[nt][0] = p[0];
                bf[nt][1] = p[4];
            }
#pragma unroll
            for (int mt = 0; mt < 4; mt++)
#pragma unroll
                for (int nt = 0; nt < 4; nt++)
                    MMA_F16(acc[mt][nt], af[mt], bf[nt][0], bf[nt][1]);
        }
        __syncthreads();
        if (i + 2 < NCH) load_tile(i + 2, s);
    }

#pragma unroll
    for (int mt = 0; mt < 4; mt++) {
        const int row0 = brow + wm + mt * 16 + g;
#pragma unroll
        for (int nt = 0; nt < 4; nt++) {
            const int col = bcol + wn + nt * 8 + t4 * 2;
            const float bx = bias[col], by = bias[col + 1];
#pragma unroll
            for (int hh = 0; hh < 2; hh++) {
                const int row = row0 + hh * 8;
                float vx = acc[mt][nt][2 * hh]     + bx;
                float vy = acc[mt][nt][2 * hh + 1] + by;
                if (GELU) {
                    vx = 0.5f * vx * (1.0f + erff(vx * 0.70710678118654752f));
                    vy = 0.5f * vy * (1.0f + erff(vy * 0.70710678118654752f));
                }
                size_t go = (size_t)row * N + col;
                if (RES) {
                    __half2 rv = *(const __half2*)&res[go];
                    vx += __half2float(rv.x); vy += __half2float(rv.y);
                }
                if (HOUT) {
                    *(__half2*)&((__half*)Cv)[go] = __floats2half2_rn(vx, vy);
                } else {
                    float2 o; o.x = vx; o.y = vy;
                    *(float2*)&((float*)Cv)[go] = o;
                }
            }
        }
    }
}

// ---------------------------------------------------------------------------
// fp16 flash attention (frozen R11 version: 64 q/CTA, 4 warps, smem P)
// ---------------------------------------------------------------------------
#define ATT_SMEM_BYTES (6 * 64 * SMW * 4)

__global__ __launch_bounds__(128) void attention_mma_kernel(
    const __half* __restrict__ qkv, __half* __restrict__ out) {
    extern __shared__ __align__(16) uint32_t smw[];
    uint32_t* Qw = smw;
    uint32_t* Pw = smw + 64 * SMW;
    uint32_t* Kw = smw + 2 * 64 * SMW;
    uint32_t* Vw = smw + 4 * 64 * SMW;

    const int b = blockIdx.z, h = blockIdx.y, qt = blockIdx.x;
    const int tid = threadIdx.x, wid = tid >> 5, lane = tid & 31;
    const int g = lane >> 2, t4 = lane & 3;

    const uint32_t sK = smem_u32(Kw), sV = smem_u32(Vw);

    const __half* Qg = qkv + (size_t)(b * SEQ + qt * 64) * QKVN + h * HD;
    const __half* Kg = qkv + (size_t)b * SEQ * QKVN + DIM     + h * HD;
    const __half* Vg = qkv + (size_t)b * SEQ * QKVN + 2 * DIM + h * HD;

    {
        const __half2 sc = __float2half2_rn(0.125f);
#pragma unroll
        for (int it = 0; it < 4; it++) {
            int id = it * 128 + tid;
            int r = id >> 3, cc = id & 7;
            uint4 v = *(const uint4*)(Qg + (size_t)r * QKVN + cc * 8);
            __half2* hv = (__half2*)&v;
            hv[0] = __hmul2(hv[0], sc); hv[1] = __hmul2(hv[1], sc);
            hv[2] = __hmul2(hv[2], sc); hv[3] = __hmul2(hv[3], sc);
            *(uint4*)&Qw[r * SMW + cc * 4] = v;
        }
    }

    auto loadKV = [&](int kb, int s) {
#pragma unroll
        for (int it = 0; it < 4; it++) {
            int id = it * 128 + tid;
            int r = id >> 3, cc = id & 7;
            uint32_t off = (uint32_t)(((s * 64 + r) * SMW + cc * 4) * 4);
            const __half* gk = Kg + (size_t)(kb * 64 + r) * QKVN + cc * 8;
            asm volatile("cp.async.cg.shared.global [%0], [%1], 16;"
                         :: "r"(sK + off), "l"(gk));
            const __half* gv = Vg + (size_t)(kb * 64 + r) * QKVN + cc * 8;
            asm volatile("cp.async.cg.shared.global [%0], [%1], 16;"
                         :: "r"(sV + off), "l"(gv));
        }
        asm volatile("cp.async.commit_group;" ::: "memory");
    };

    loadKV(0, 0);
    loadKV(1, 1);
    __syncthreads();

    const int m0row = wid * 16 + g;
    uint32_t af[4][4];
#pragma unroll
    for (int kt = 0; kt < 4; kt++) {
        const uint32_t* p = Qw + m0row * SMW + kt * 8 + t4;
        af[kt][0] = p[0];
        af[kt][1] = p[8 * SMW];
        af[kt][2] = p[4];
        af[kt][3] = p[8 * SMW + 4];
    }

    const int vrow16 = lane & 15;
    const int vcolw  = (lane >> 4) * 4;

    float of[8][4];
#pragma unroll
    for (int nt = 0; nt < 8; nt++)
#pragma unroll
        for (int r = 0; r < 4; r++) of[nt][r] = 0.f;
    float m0 = -INFINITY, m1 = -INFINITY, l0 = 0.f, l1 = 0.f;

    for (int i = 0; i < 16; i++) {
        const int s = i & 1;
        if (i < 15) asm volatile("cp.async.wait_group 1;" ::: "memory");
        else        asm volatile("cp.async.wait_group 0;" ::: "memory");
        __syncthreads();

        const uint32_t* ks = Kw + s * 64 * SMW;

        float sf[8][4];
#pragma unroll
        for (int nt = 0; nt < 8; nt++)
#pragma unroll
            for (int r = 0; r < 4; r++) sf[nt][r] = 0.f;
#pragma unroll
        for (int kt = 0; kt < 4; kt++) {
#pragma unroll
            for (int nt = 0; nt < 8; nt++) {
                const uint32_t* p = ks + (nt * 8 + g) * SMW + kt * 8 + t4;
                MMA_F16(sf[nt], af[kt], p[0], p[4]);
            }
        }

        float tm0 = -INFINITY, tm1 = -INFINITY;
#pragma unroll
        for (int nt = 0; nt < 8; nt++) {
            tm0 = fmaxf(tm0, fmaxf(sf[nt][0], sf[nt][1]));
            tm1 = fmaxf(tm1, fmaxf(sf[nt][2], sf[nt][3]));
        }
        tm0 = fmaxf(tm0, __shfl_xor_sync(0xffffffffu, tm0, 1));
        tm0 = fmaxf(tm0, __shfl_xor_sync(0xffffffffu, tm0, 2));
        tm1 = fmaxf(tm1, __shfl_xor_sync(0xffffffffu, tm1, 1));
        tm1 = fmaxf(tm1, __shfl_xor_sync(0xffffffffu, tm1, 2));
        const float nm0 = fmaxf(m0, tm0), nm1 = fmaxf(m1, tm1);
        const float a0 = __expf(m0 - nm0), a1 = __expf(m1 - nm1);

        float rs0 = 0.f, rs1 = 0.f;
        uint32_t* pp0 = Pw + m0row * SMW + t4;
        uint32_t* pp1 = Pw + (m0row + 8) * SMW + t4;
#pragma unroll
        for (int nt = 0; nt < 8; nt++) {
            float p0 = __expf(sf[nt][0] - nm0);
            float p1 = __expf(sf[nt][1] - nm0);
            float p2 = __expf(sf[nt][2] - nm1);
            float p3 = __expf(sf[nt][3] - nm1);
            rs0 += p0 + p1; rs1 += p2 + p3;
            ((__half2*)pp0)[0] = __floats2half2_rn(p0, p1);
            ((__half2*)pp1)[0] = __floats2half2_rn(p2, p3);
            pp0 += 4; pp1 += 4;
        }
        rs0 += __shfl_xor_sync(0xffffffffu, rs0, 1);
        rs0 += __shfl_xor_sync(0xffffffffu, rs0, 2);
        rs1 += __shfl_xor_sync(0xffffffffu, rs1, 1);
        rs1 += __shfl_xor_sync(0xffffffffu, rs1, 2);
        l0 = l0 * a0 + rs0;
        l1 = l1 * a1 + rs1;
#pragma unroll
        for (int nt = 0; nt < 8; nt++) {
            of[nt][0] *= a0; of[nt][1] *= a0;
            of[nt][2] *= a1; of[nt][3] *= a1;
        }
        m0 = nm0; m1 = nm1;
        __syncthreads();

#pragma unroll
        for (int kk = 0; kk < 4; kk++) {
            const uint32_t* pw = Pw + m0row * SMW + kk * 8 + t4;
            uint32_t pf[4];
            pf[0] = pw[0];
            pf[1] = pw[8 * SMW];
            pf[2] = pw[4];
            pf[3] = pw[8 * SMW + 4];
            const uint32_t vrowbase = (uint32_t)(((s * 64 + kk * 16 + vrow16) * SMW + vcolw) * 4);
#pragma unroll
            for (int ntp = 0; ntp < 4; ntp++) {
                uint32_t b00, b01, b10, b11;
                uint32_t addr = sV + vrowbase + (uint32_t)(ntp * 8 * 4);
                asm volatile(
                    "ldmatrix.sync.aligned.m8n8.x4.trans.shared.b16 "
                    "{%0,%1,%2,%3}, [%4];"
                    : "=r"(b00), "=r"(b01), "=r"(b10), "=r"(b11)
                    : "r"(addr));
                MMA_F16(of[2 * ntp],     pf, b00, b01);
                MMA_F16(of[2 * ntp + 1], pf, b10, b11);
            }
        }
        __syncthreads();
        if (i + 2 < 16) loadKV(i + 2, s);
    }

    const float i0 = 1.f / l0, i1 = 1.f / l1;
    const int row = b * SEQ + qt * 64 + m0row;
#pragma unroll
    for (int nt = 0; nt < 8; nt++) {
        const int col = h * HD + nt * 8 + 2 * t4;
        *(__half2*)&out[(size_t)row * DIM + col] =
            __floats2half2_rn(of[nt][0] * i0, of[nt][1] * i0);
        *(__half2*)&out[(size_t)(row + 8) * DIM + col] =
            __floats2half2_rn(of[nt][2] * i1, of[nt][3] * i1);
    }
}

// ---------------------------------------------------------------------------
// Repack / transpose (frozen)
// ---------------------------------------------------------------------------
__global__ void repack_qkv_t_kernel(const float* __restrict__ Wq, const float* __restrict__ bq,
                                    const float* __restrict__ Wk, const float* __restrict__ bk,
                                    const float* __restrict__ Wv, const float* __restrict__ bv) {
    int idx = blockIdx.x * blockDim.x + threadIdx.x;
    const int total = QKVN * DIM;
    if (idx < total) {
        int n = idx / DIM;
        int d = idx % DIM;
        int t  = n / DIM;
        int h  = (n % DIM) / HD;
        int kk = n % HD;
        const float* W = (t == 0) ? Wq : (t == 1) ? Wk : Wv;
        g_wqkv_t[idx] = __float2half_rn(W[(h * DIM + d) * HD + kk]);
    }
    if (idx < QKVN) {
        int t  = idx / DIM;
        int h  = (idx % DIM) / HD;
        int kk = idx % HD;
        const float* bb = (t == 0) ? bq : (t == 1) ? bk : bv;
        g_bqkv[idx] = bb[h * HD + kk];
    }
}

__global__ void transpose_kernel(const float* __restrict__ in, __half* __restrict__ out,
                                 int R, int C) {
    __shared__ float t[32][33];
    int c0 = blockIdx.x * 32, r0 = blockIdx.y * 32;
    int x = c0 + threadIdx.x;
    for (int dy = threadIdx.y; dy < 32; dy += 8) {
        int r = r0 + dy;
        if (r < R && x < C) t[dy][threadIdx.x] = in[(size_t)r * C + x];
    }
    __syncthreads();
    int y = r0 + threadIdx.x;
    for (int dx = threadIdx.y; dx < 32; dx += 8) {
        int c = c0 + dx;
        if (c < C && y < R) out[(size_t)c * R + y] = __float2half_rn(t[threadIdx.x][dx]);
    }
}

// ---------------------------------------------------------------------------
// Warp-per-row LayerNorm (ddof=1): 8 rows per 256-thr block, 6 float4/thread
// (MLP=6), shuffle-only reductions, no block barriers. fp16 out.
// ---------------------------------------------------------------------------
__global__ __launch_bounds__(256) void layernorm_warp_kernel(
    const float* __restrict__ X, const float* __restrict__ gamma,
    const float* __restrict__ beta, __half* __restrict__ Y) {
    const int wid = threadIdx.x >> 5, lane = threadIdx.x & 31;
    const int row = blockIdx.x * 8 + wid;
    const float4* x4 = (const float4*)(X + (size_t)row * DIM);

    float4 v[6];
#pragma unroll
    for (int j = 0; j < 6; j++) v[j] = x4[lane + 32 * j];

    float s = 0.f;
#pragma unroll
    for (int j = 0; j < 6; j++) s += (v[j].x + v[j].y) + (v[j].z + v[j].w);
#pragma unroll
    for (int o = 16; o > 0; o >>= 1) s += __shfl_xor_sync(0xffffffffu, s, o);
    const float mean = s / (float)DIM;

    float vv = 0.f;
#pragma unroll
    for (int j = 0; j < 6; j++) {
        float dx = v[j].x - mean, dy = v[j].y - mean;
        float dz = v[j].z - mean, dw = v[j].w - mean;
        vv += dx * dx + dy * dy + dz * dz + dw * dw;
    }
#pragma unroll
    for (int o = 16; o > 0; o >>= 1) vv += __shfl_xor_sync(0xffffffffu, vv, o);
    const float inv = rsqrtf(vv / (float)(DIM - 1) + LN_EPS);

    const float4* g4 = (const float4*)gamma;
    const float4* b4 = (const float4*)beta;
    uint2* y4 = (uint2*)(Y + (size_t)row * DIM);
#pragma unroll
    for (int j = 0; j < 6; j++) {
        const int idx = lane + 32 * j;
        float4 gg = g4[idx], bb = b4[idx];
        __half2 h0 = __floats2half2_rn(gg.x * (v[j].x - mean) * inv + bb.x,
                                       gg.y * (v[j].y - mean) * inv + bb.y);
        __half2 h1 = __floats2half2_rn(gg.z * (v[j].z - mean) * inv + bb.z,
                                       gg.w * (v[j].w - mean) * inv + bb.w);
        uint2 o; o.x = h2u(h0); o.y = h2u(h1);
        y4[idx] = o;
    }
}

// ---------------------------------------------------------------------------
// Host launch — weight transposes forked to a prep stream, joined before
// o-proj (first consumer). Streams/events created once on the first
// (non-captured) correctness call; capture sees only record/wait nodes.
// ---------------------------------------------------------------------------
extern "C" void kernel_launch(void* const* d_in, const int* in_sizes, int n_in,
                              void* d_out, int out_size) {
    const float* x   = (const float*)d_in[0];
    const float* Wq  = (const float*)d_in[1];
    const float* bq  = (const float*)d_in[2];
    const float* Wk  = (const float*)d_in[3];
    const float* bk  = (const float*)d_in[4];
    const float* Wv  = (const float*)d_in[5];
    const float* bv  = (const float*)d_in[6];
    const float* Wo  = (const float*)d_in[7];
    const float* bo  = (const float*)d_in[8];
    const float* W1  = (const float*)d_in[9];
    const float* b1  = (const float*)d_in[10];
    const float* W2  = (const float*)d_in[11];
    const float* b2  = (const float*)d_in[12];
    const float* g1  = (const float*)d_in[13];
    const float* be1 = (const float*)d_in[14];
    const float* g2  = (const float*)d_in[15];
    const float* be2 = (const float*)d_in[16];
    float* out = (float*)d_out;

    __half *xn, *qkv, *att, *y2, *hbuf, *wqkv_t, *wo_t, *w1_t, *w2_t;
    float  *y1, *bqkv;
    cudaGetSymbolAddress((void**)&xn,     g_xn);
    cudaGetSymbolAddress((void**)&qkv,    g_qkv);
    cudaGetSymbolAddress((void**)&att,    g_att);
    cudaGetSymbolAddress((void**)&y1,     g_y1);
    cudaGetSymbolAddress((void**)&y2,     g_y2);
    cudaGetSymbolAddress((void**)&hbuf,   g_h);
    cudaGetSymbolAddress((void**)&wqkv_t, g_wqkv_t);
    cudaGetSymbolAddress((void**)&bqkv,   g_bqkv);
    cudaGetSymbolAddress((void**)&wo_t,   g_wo_t);
    cudaGetSymbolAddress((void**)&w1_t,   g_w1_t);
    cudaGetSymbolAddress((void**)&w2_t,   g_w2_t);

    cudaFuncSetAttribute(h_gemm_kernel<false, false, true>,
                         cudaFuncAttributeMaxDynamicSharedMemorySize, GEMM_SMEM_BYTES);
    cudaFuncSetAttribute(h_gemm_kernel<true, false, true>,
                         cudaFuncAttributeMaxDynamicSharedMemorySize, GEMM_SMEM_BYTES);
    cudaFuncSetAttribute(h_gemm_kernel<false, true, false>,
                         cudaFuncAttributeMaxDynamicSharedMemorySize, GEMM_SMEM_BYTES);
    cudaFuncSetAttribute(attention_mma_kernel,
                         cudaFuncAttributeMaxDynamicSharedMemorySize, ATT_SMEM_BYTES);

    static cudaStream_t sPrep = nullptr;
    static cudaEvent_t  evFork = nullptr, evJoin = nullptr;
    if (sPrep == nullptr) {
        cudaStreamCreateWithFlags(&sPrep, cudaStreamNonBlocking);
        cudaEventCreateWithFlags(&evFork, cudaEventDisableTiming);
        cudaEventCreateWithFlags(&evJoin, cudaEventDisableTiming);
    }

    // fork: weight transposes on prep stream (consumers: steps 4/6/7)
    cudaEventRecord(evFork, 0);
    cudaStreamWaitEvent(sPrep, evFork, 0);
    {
        dim3 blk(32, 8);
        transpose_kernel<<<dim3(DIM / 32, DIM / 32), blk, 0, sPrep>>>(Wo, wo_t, DIM, DIM);
        transpose_kernel<<<dim3(D4 / 32, DIM / 32), blk, 0, sPrep>>>(W1, w1_t, DIM, D4);
        transpose_kernel<<<dim3(DIM / 32, D4 / 32), blk, 0, sPrep>>>(W2, w2_t, D4, DIM);
    }
    cudaEventRecord(evJoin, sPrep);

    // main chain
    {
        int total = QKVN * DIM;
        repack_qkv_t_kernel<<<(total + 255) / 256, 256>>>(Wq, bq, Wk, bk, Wv, bv);
    }
    // 1. ln1 -> half xn (warp-per-row)
    layernorm_warp_kernel<<<BS / 8, 256>>>(x, g1, be1, xn);
    // 2. fused QKV gemm -> half qkv
    h_gemm_kernel<false, false, true><<<dim3(QKVN / 128, BS / 128), 256, GEMM_SMEM_BYTES>>>(
        xn, wqkv_t, bqkv, nullptr, qkv, BS, QKVN, DIM);
    // 3. attention -> half att
    attention_mma_kernel<<<dim3(SEQ / 64, NH, 8), 128, ATT_SMEM_BYTES>>>(qkv, att);

    // join: transposes must be done before o-proj
    cudaStreamWaitEvent(0, evJoin, 0);

    // 4. o-proj + residual(xn) -> float y1
    h_gemm_kernel<false, true, false><<<dim3(DIM / 128, BS / 128), 256, GEMM_SMEM_BYTES>>>(
        att, wo_t, bo, xn, y1, BS, DIM, DIM);
    // 5. ln2 -> half y2
    layernorm_warp_kernel<<<BS / 8, 256>>>(y1, g2, be2, y2);
    // 6. ffn up + gelu -> half h
    h_gemm_kernel<true, false, true><<<dim3(D4 / 128, BS / 128), 256, GEMM_SMEM_BYTES>>>(
        y2, w1_t, b1, nullptr, hbuf, BS, D4, DIM);
    // 7. ffn down + residual(y2) -> float out
    h_gemm_kernel<false, true, false><<<dim3(DIM / 128, BS / 128), 256, GEMM_SMEM_BYTES>>>(
        hbuf, w2_t, b2, y2, out, BS, DIM, D4);
}